// round 4
// baseline (speedup 1.0000x reference)
#include <cuda_runtime.h>
#include <math.h>
#include <float.h>

#define T2       2
#define BATCH    256
#define NSAMP    80000
#define NPERSEG  100
#define NFREQ    51
#define NSEG     800
#define COLS     (BATCH * NFREQ)      // 13056 = 51*256
#define GSEG     5                    // segments per fused block
#define FBLKS    (T2 * (NSEG / GSEG)) // 320
#define WARPS    16
#define WAVE     (WARPS * 3)          // 48 instances per wave
#define NWAVE    ((BATCH + WAVE - 1) / WAVE)  // 6
#define STRIDE_W 120                  // words per instance slot in buf (480 B)

#define TWO_PI 6.28318530717958647692f

// w10^k = e^{-2*pi*i*k/10} = (C10[k], -S10[k]) — compile-time immediates
__device__ constexpr float C10[10] = {
     1.0f,  0.80901699437494745f,  0.30901699437494745f, -0.30901699437494745f,
    -0.80901699437494745f, -1.0f, -0.80901699437494745f, -0.30901699437494745f,
     0.30901699437494745f,  0.80901699437494745f };
__device__ constexpr float S10[10] = {
     0.0f,  0.58778525229247314f,  0.95105651629515353f,  0.95105651629515353f,
     0.58778525229247314f,  0.0f, -0.58778525229247314f, -0.95105651629515353f,
    -0.95105651629515353f, -0.58778525229247314f };

__device__ float  g_colsum[T2][COLS];
__device__ double g_saTot[T2];
__device__ double g_acc[2];   // [0]=sum SF*SR, [1]=sum SF*SF

__device__ __forceinline__ float sclog(float p) {
    float lx = __logf(p);
    float s  = (lx > 0.0f) ? 1.0f : ((lx < 0.0f) ? -1.0f : 0.0f);
    return s * fmaxf(fabsf(lx), 1e-6f);
}

// ---------------------------------------------------------------------------
__global__ __launch_bounds__(256) void zero_kernel() {
    int i = blockIdx.x * 256 + threadIdx.x;
    if (i < T2 * COLS) ((float*)g_colsum)[i] = 0.0f;
    if (i < T2) g_saTot[i] = 0.0;
    if (i < 2)  g_acc[i] = 0.0;
}

// ---------------------------------------------------------------------------
// Fused: for each of GSEG segments — Welch window -> 10x10 CT rDFT(100) ->
// |.|^2 -> signed clamp log into smem, then in-smem group normalization with
// register-accumulated column sums. One atomic batch per block at the end.
//
// Dynamic smem layout (floats):
//   tws   : 200   (float2[100], 8B aligned at base)
//   buf   : WAVE*STRIDE_W = 5760   (xs/Ysh aliased, per-instance 480B slot)
//   psd_s : COLS = 13056
//   wnd   : 100
//   mn2   : 512, mx2 : 512, red : 512
#define SMEM_FLOATS (200 + WAVE * STRIDE_W + COLS + 100 + 512 + 512 + 512)
#define SMEM_BYTES  (SMEM_FLOATS * 4)

__global__ __launch_bounds__(512) void fused_kernel(const float* __restrict__ fake,
                                                    const float* __restrict__ real_) {
    extern __shared__ float sm[];
    float2* tws   = (float2*)sm;             // 100 float2
    float*  buf   = sm + 200;                // 5760
    float*  psd_s = buf + WAVE * STRIDE_W;   // 13056
    float*  wnd   = psd_s + COLS;            // 100
    float*  mn2   = wnd + 100;               // [2][256]
    float*  mx2   = mn2 + 512;               // [2][256]
    float*  red   = mx2 + 512;               // 512

    const int tid  = threadIdx.x;
    const int t    = blockIdx.x / (NSEG / GSEG);
    const int sgrp = blockIdx.x % (NSEG / GSEG);
    const float* __restrict__ base = (t == 0) ? fake : real_;

    if (tid < NPERSEG) {
        float s, c;
        sincosf(TWO_PI * 0.01f * (float)tid, &s, &c);
        tws[tid] = make_float2(c, -s);
        wnd[tid] = 1.0f - c;                  // hann(periodic)*2
    }
    __syncthreads();

    const int warp = tid >> 5, lane = tid & 31;
    const int ik   = lane / 10;               // 0..2 (3 for lanes 30/31)
    const int role = (lane < 30) ? (lane - ik * 10) : 0;
    const bool alive = (lane < 30);

    // Hoisted stage-2 twiddles: tw100[role*q], loop-invariant per lane.
    float2 twm[10];
    #pragma unroll
    for (int q = 0; q < 10; ++q) twm[q] = tws[role * q];

    // Norm-phase identity
    const int h  = tid >> 8;                  // 0/1
    const int r  = tid & 255;
    const int j0 = h * 26;
    const int jn = (h == 0) ? 26 : 25;        // 26 + 25 = 51

    float csum[26];
    #pragma unroll
    for (int jj = 0; jj < 26; ++jj) csum[jj] = 0.0f;
    double ssq = 0.0;

    for (int g = 0; g < GSEG; ++g) {
        const int seg = sgrp * GSEG + g;

        // ---------------- DFT waves ----------------
        for (int w = 0; w < NWAVE; ++w) {
            const int bwave = w * WAVE;
            // stage 0: load+clamp+window this warp's 3 instances
            #pragma unroll
            for (int k = 0; k < 3; ++k) {
                const int b = bwave + warp * 3 + k;
                if (b < BATCH) {
                    const float* __restrict__ src = base + (size_t)b * NSAMP + seg * NPERSEG;
                    float* xs = buf + (warp * 3 + k) * STRIDE_W;
                    for (int i = lane; i < NPERSEG; i += 32)
                        xs[i] = fmaxf(src[i], 1e-6f) * wnd[i];
                }
            }
            __syncwarp();

            const int binst = bwave + warp * 3 + ik;
            const bool act  = alive && (binst < BATCH);
            float* slot = buf + (warp * 3 + ik) * STRIDE_W;

            // stage 1: read decimated samples to regs
            float xr[10];
            if (act) {
                #pragma unroll
                for (int a = 0; a < 10; ++a) xr[a] = slot[a * 10 + role];
            }
            __syncwarp();   // xs fully consumed -> safe to alias with Ysh

            if (act) {
                float2* Y = (float2*)slot;    // [10][6]
                #pragma unroll
                for (int rr = 0; rr < 6; ++rr) {
                    float re = 0.0f, im = 0.0f;
                    #pragma unroll
                    for (int a = 0; a < 10; ++a) {
                        const int k = (rr * a) % 10;
                        re = fmaf(xr[a],  C10[k], re);
                        im = fmaf(xr[a], -S10[k], im);
                    }
                    Y[role * 6 + rr] = make_float2(re, im);
                }
            }
            __syncwarp();

            // stage 2: Z[q] = tw100[m q] * Y~[q]; X[10j+m] = sum_q w10^{jq} Z[q]
            if (act) {
                const float2* Y = (const float2*)slot;
                const int   m  = role;
                const int   c  = (m <= 5) ? m : 10 - m;
                const float cj = (m <= 5) ? 1.0f : -1.0f;
                float Zr[10], Zi[10];
                #pragma unroll
                for (int q = 0; q < 10; ++q) {
                    float2 y = Y[q * 6 + c];
                    float  yi = y.y * cj;
                    float2 e = twm[q];
                    Zr[q] = fmaf(e.x, y.x, -e.y * yi);
                    Zi[q] = fmaf(e.x, yi,   e.y * y.x);
                }
                float* out = psd_s + binst * NFREQ;
                #pragma unroll
                for (int j = 0; j < 5; ++j) {
                    float Xr = 0.0f, Xi = 0.0f;
                    #pragma unroll
                    for (int q = 0; q < 10; ++q) {
                        const int k = (j * q) % 10;
                        Xr = fmaf(Zr[q],  C10[k], Xr);
                        Xr = fmaf(Zi[q],  S10[k], Xr);
                        Xi = fmaf(Zi[q],  C10[k], Xi);
                        Xi = fmaf(Zr[q], -S10[k], Xi);
                    }
                    out[m + 10 * j] = sclog(fmaf(Xr, Xr, Xi * Xi));
                }
                if (m == 0) {                 // f = 50: w10^{5q} = ±1
                    float Xr = 0.0f, Xi = 0.0f;
                    #pragma unroll
                    for (int q = 0; q < 10; ++q) {
                        const int k = (5 * q) % 10;
                        Xr = fmaf(Zr[q], C10[k], Xr);
                        Xi = fmaf(Zi[q], C10[k], Xi);
                    }
                    out[50] = sclog(fmaf(Xr, Xr, Xi * Xi));
                }
            }
            __syncwarp();   // slot dead before next wave's stage-0 writes
        }
        __syncthreads();    // psd_s complete for this segment

        // ---------------- normalization ----------------
        // group r = flat indices { j*256 + r : j = 0..50 } within this segment
        float mn = FLT_MAX, mx = -FLT_MAX;
        for (int jj = 0; jj < jn; ++jj) {
            float x = psd_s[(j0 + jj) * 256 + r];
            mn = fminf(mn, x);
            mx = fmaxf(mx, x);
        }
        mn2[h * 256 + r] = mn;
        mx2[h * 256 + r] = mx;
        __syncthreads();
        mn = fminf(mn2[r], mn2[256 + r]);
        mx = fmaxf(mx2[r], mx2[256 + r]);
        const float inv = 1.0f / (mx - mn);
        float ss = 0.0f;
        for (int jj = 0; jj < jn; ++jj) {
            float x = (psd_s[(j0 + jj) * 256 + r] - mn) * inv;
            csum[jj] += x;
            ss = fmaf(x, x, ss);
        }
        ssq += (double)ss;
        __syncthreads();    // psd_s / mn2 reusable next segment
    }

    // ---------------- per-block flush ----------------
    for (int jj = 0; jj < jn; ++jj)
        atomicAdd(&g_colsum[t][(j0 + jj) * 256 + r], csum[jj]);

    red[tid] = (float)ssq;   // ssq <= 5*51 per thread; float is plenty here? keep double path:
    __syncthreads();
    // block-reduce in double via two-stage: stash doubles in shared as pairs
    // (simpler: warp-level double reduce then atomic)
    double v = ssq;
    #pragma unroll
    for (int off = 16; off > 0; off >>= 1)
        v += __shfl_down_sync(0xffffffff, v, off);
    __shared__ double wsum[16];
    if (lane == 0) wsum[warp] = v;
    __syncthreads();
    if (warp == 0) {
        double u = (lane < 16) ? wsum[lane] : 0.0;
        #pragma unroll
        for (int off = 8; off > 0; off >>= 1)
            u += __shfl_down_sync(0xffffffff, u, off);
        if (lane == 0) atomicAdd(&g_saTot[t], u);
    }
}

// ---------------------------------------------------------------------------
__global__ __launch_bounds__(256) void dot_kernel() {
    const int i = blockIdx.x * 256 + threadIdx.x;
    double SF = (double)g_colsum[0][i];
    double SR = (double)g_colsum[1][i];
    double d = SF * SR, q = SF * SF;

    __shared__ double rd[256], rq[256];
    rd[threadIdx.x] = d; rq[threadIdx.x] = q;
    __syncthreads();
    for (int off = 128; off > 0; off >>= 1) {
        if (threadIdx.x < off) {
            rd[threadIdx.x] += rd[threadIdx.x + off];
            rq[threadIdx.x] += rq[threadIdx.x + off];
        }
        __syncthreads();
    }
    if (threadIdx.x == 0) {
        atomicAdd(&g_acc[0], rd[0]);
        atomicAdd(&g_acc[1], rq[0]);
    }
}

// ---------------------------------------------------------------------------
__global__ void final_kernel(float* __restrict__ out) {
    if (threadIdx.x == 0) {
        const double SA = g_saTot[0], SB = g_saTot[1];
        const double n  = (double)COLS;
        const double ns = (double)NSEG;
        const double m  = ns * (ns - 1.0) * 0.5;
        out[0] = (float)((SA / ns + SB / ns - 2.0 * g_acc[0] / (ns * ns)) / n);
        out[1] = (float)((ns * SA - g_acc[1]) / (n * m));
    }
}

// ---------------------------------------------------------------------------
extern "C" void kernel_launch(void* const* d_in, const int* in_sizes, int n_in,
                              void* d_out, int out_size) {
    const float* fake  = (const float*)d_in[0];
    const float* real_ = (const float*)d_in[1];
    float* out = (float*)d_out;

    cudaFuncSetAttribute(fused_kernel,
                         cudaFuncAttributeMaxDynamicSharedMemorySize, SMEM_BYTES);

    zero_kernel<<<(T2 * COLS + 255) / 256, 256>>>();
    fused_kernel<<<FBLKS, 512, SMEM_BYTES>>>(fake, real_);
    dot_kernel<<<COLS / 256, 256>>>();
    final_kernel<<<1, 32>>>(out);
}

// round 5
// speedup vs baseline: 2.9538x; 2.9538x over previous
#include <cuda_runtime.h>
#include <math.h>
#include <float.h>

#define T2       2
#define BATCH    256
#define NSAMP    80000
#define NPERSEG  100
#define NFREQ    51
#define NSEG     800
#define COLS     (BATCH * NFREQ)         // 13056 = 51*256
#define NSPB     8
#define NORMBLKS (NSEG / NSPB)           // 100
#define IPB      24                      // instances per psd block (8 warps x 3)
#define TOTAL    (T2 * NSEG * BATCH)     // 409600
#define PSDBLKS  ((TOTAL + IPB - 1) / IPB)

#define TWO_PI 6.28318530717958647692f

// w10^k = e^{-2*pi*i*k/10} = (C10[k], -S10[k]) — compile-time immediates
__device__ constexpr float C10[10] = {
     1.0f,  0.80901699437494745f,  0.30901699437494745f, -0.30901699437494745f,
    -0.80901699437494745f, -1.0f, -0.80901699437494745f, -0.30901699437494745f,
     0.30901699437494745f,  0.80901699437494745f };
__device__ constexpr float S10[10] = {
     0.0f,  0.58778525229247314f,  0.95105651629515353f,  0.95105651629515353f,
     0.58778525229247314f,  0.0f, -0.58778525229247314f, -0.95105651629515353f,
    -0.95105651629515353f, -0.58778525229247314f };

// Scratch: signed-clamp-log PSD (unnormalized). 83.6 MB.
__device__ float  g_L[T2][NSEG][COLS];
__device__ float  g_colsum[T2][COLS];
__device__ double g_saTot[T2];
__device__ double g_acc[2];   // [0]=sum SF*SR, [1]=sum SF*SF

__device__ __forceinline__ float sclog(float p) {
    float lx = __logf(p);                 // MUFU.LG2 path — warp-granular, cheap
    float s  = (lx > 0.0f) ? 1.0f : ((lx < 0.0f) ? -1.0f : 0.0f);
    return s * fmaxf(fabsf(lx), 1e-6f);
}

// ---------------------------------------------------------------------------
__global__ __launch_bounds__(256) void zero_kernel() {
    int i = blockIdx.x * 256 + threadIdx.x;
    if (i < T2 * COLS) ((float*)g_colsum)[i] = 0.0f;
    if (i < T2) g_saTot[i] = 0.0;
    if (i < 2)  g_acc[i] = 0.0;
}

// ---------------------------------------------------------------------------
// Kernel A: Welch -> 10x10 Cooley-Tukey rDFT(100) -> |.|^2 -> signed clamp log.
// Warp = 3 segment-instances, 10 active lanes each. Stage1 lane=q (sample
// phase), stage2 lane=m (output class). Inner twiddles are immediates.
__global__ __launch_bounds__(256) void psd_kernel(const float* __restrict__ fake,
                                                  const float* __restrict__ real_) {
    __shared__ float  wnd[NPERSEG];
    __shared__ float2 tws[NPERSEG];          // e^{-2 pi i k/100}
    __shared__ float  xs[IPB][NPERSEG];
    __shared__ float2 Ysh[IPB][10][6];
    __shared__ float  psd_s[IPB][NFREQ];

    const int tid = threadIdx.x;
    if (tid < NPERSEG) {
        float s, c;
        sincosf(TWO_PI * 0.01f * (float)tid, &s, &c);
        tws[tid] = make_float2(c, -s);
        wnd[tid] = 1.0f - c;                 // hann(periodic)*2
    }
    __syncthreads();

    const int warp = tid >> 5, lane = tid & 31;
    const int base_inst = warp * 3;
    const long gbase = (long)blockIdx.x * IPB + base_inst;

    // ---- stage 0: coalesced load + clamp + window into smem ----
    #pragma unroll
    for (int k = 0; k < 3; ++k) {
        long g = gbase + k;
        if (g >= TOTAL) break;
        int t   = (int)(g / (NSEG * BATCH));
        int rem = (int)(g - (long)t * (NSEG * BATCH));
        int seg = rem / BATCH, b = rem - seg * BATCH;
        const float* __restrict__ src =
            ((t == 0) ? fake : real_) + (size_t)b * NSAMP + (size_t)seg * NPERSEG;
        for (int i = lane; i < NPERSEG; i += 32)
            xs[base_inst + k][i] = fmaxf(src[i], 1e-6f) * wnd[i];
    }
    __syncwarp();

    const int  ik   = lane / 10;             // 0..2
    const int  role = lane - ik * 10;        // 0..9
    const int  inst = base_inst + ik;
    const bool act  = (lane < 30) && (gbase + ik < TOTAL);

    // ---- stage 1: Y[q][r] = sum_a x[10a+q] w10^{ra}, r=0..5 ----
    if (act) {
        float xr[10];
        #pragma unroll
        for (int a = 0; a < 10; ++a) xr[a] = xs[inst][a * 10 + role];
        #pragma unroll
        for (int r = 0; r < 6; ++r) {
            float re = 0.0f, im = 0.0f;
            #pragma unroll
            for (int a = 0; a < 10; ++a) {
                const int k = (r * a) % 10;
                re = fmaf(xr[a],  C10[k], re);
                im = fmaf(xr[a], -S10[k], im);
            }
            Ysh[inst][role][r] = make_float2(re, im);
        }
    }
    __syncwarp();

    // ---- stage 2: Z[q] = tw100[m q] * Y~[q];  X[10j+m] = sum_q w10^{jq} Z[q]
    if (act) {
        const int   m  = role;
        const int   c  = (m <= 5) ? m : 10 - m;
        const float cj = (m <= 5) ? 1.0f : -1.0f;
        float Zr[10], Zi[10];
        #pragma unroll
        for (int q = 0; q < 10; ++q) {
            float2 y = Ysh[inst][q][c];
            float  yi = y.y * cj;
            float2 e = tws[m * q];
            Zr[q] = fmaf(e.x, y.x, -e.y * yi);
            Zi[q] = fmaf(e.x, yi,   e.y * y.x);
        }
        #pragma unroll
        for (int j = 0; j < 5; ++j) {
            float Xr = 0.0f, Xi = 0.0f;
            #pragma unroll
            for (int q = 0; q < 10; ++q) {
                const int k = (j * q) % 10;
                Xr = fmaf(Zr[q],  C10[k], Xr);
                Xr = fmaf(Zi[q],  S10[k], Xr);
                Xi = fmaf(Zi[q],  C10[k], Xi);
                Xi = fmaf(Zr[q], -S10[k], Xi);
            }
            psd_s[inst][m + 10 * j] = sclog(fmaf(Xr, Xr, Xi * Xi));
        }
        if (m == 0) {                         // f = 50: w10^{5q} = ±1
            float Xr = 0.0f, Xi = 0.0f;
            #pragma unroll
            for (int q = 0; q < 10; ++q) {
                const int k = (5 * q) % 10;
                Xr = fmaf(Zr[q], C10[k], Xr);
                Xi = fmaf(Zi[q], C10[k], Xi);
            }
            psd_s[inst][50] = sclog(fmaf(Xr, Xr, Xi * Xi));
        }
    }
    __syncwarp();

    // ---- stage 3: coalesced write-out ----
    for (int i = lane; i < 3 * NFREQ; i += 32) {
        int k = i / NFREQ, f = i - k * NFREQ;
        long gg = gbase + k;
        if (gg >= TOTAL) break;
        int t   = (int)(gg / (NSEG * BATCH));
        int rem = (int)(gg - (long)t * (NSEG * BATCH));
        int seg = rem / BATCH, b = rem - seg * BATCH;
        g_L[t][seg][b * NFREQ + f] = psd_s[base_inst + k][f];
    }
}

// ---------------------------------------------------------------------------
// Kernel B: fused per-segment normalize + column sums + sum of squares.
__global__ __launch_bounds__(256) void norm_kernel() {
    const int blk = blockIdx.x;
    const int t   = blk / NORMBLKS;
    const int c   = blk % NORMBLKS;
    const int r   = threadIdx.x;

    float csum[NFREQ];
    #pragma unroll
    for (int j = 0; j < NFREQ; ++j) csum[j] = 0.0f;
    float ssq = 0.0f;

    for (int k = 0; k < NSPB; ++k) {
        const int s = c * NSPB + k;
        const float* __restrict__ L = g_L[t][s];
        float v[NFREQ];
        float mn = FLT_MAX, mx = -FLT_MAX;
        #pragma unroll
        for (int j = 0; j < NFREQ; ++j) {
            float x = L[j * 256 + r];
            v[j] = x;
            mn = fminf(mn, x);
            mx = fmaxf(mx, x);
        }
        const float inv = 1.0f / (mx - mn);
        #pragma unroll
        for (int j = 0; j < NFREQ; ++j) {
            float x = (v[j] - mn) * inv;
            csum[j] += x;
            ssq = fmaf(x, x, ssq);
        }
    }

    #pragma unroll
    for (int j = 0; j < NFREQ; ++j)
        atomicAdd(&g_colsum[t][j * 256 + r], csum[j]);

    __shared__ float red[256];
    red[r] = ssq;
    __syncthreads();
    for (int off = 128; off > 0; off >>= 1) {
        if (r < off) red[r] += red[r + off];
        __syncthreads();
    }
    if (r == 0) atomicAdd(&g_saTot[t], (double)red[0]);
}

// ---------------------------------------------------------------------------
// Kernel C: parallel dot products over column sums. grid = 51 (COLS/256).
__global__ __launch_bounds__(256) void dot_kernel() {
    const int i = blockIdx.x * 256 + threadIdx.x;
    double SF = (double)g_colsum[0][i];
    double SR = (double)g_colsum[1][i];
    double d = SF * SR, q = SF * SF;

    __shared__ double rd[256], rq[256];
    rd[threadIdx.x] = d; rq[threadIdx.x] = q;
    __syncthreads();
    for (int off = 128; off > 0; off >>= 1) {
        if (threadIdx.x < off) {
            rd[threadIdx.x] += rd[threadIdx.x + off];
            rq[threadIdx.x] += rq[threadIdx.x + off];
        }
        __syncthreads();
    }
    if (threadIdx.x == 0) {
        atomicAdd(&g_acc[0], rd[0]);
        atomicAdd(&g_acc[1], rq[0]);
    }
}

// ---------------------------------------------------------------------------
__global__ void final_kernel(float* __restrict__ out) {
    if (threadIdx.x == 0) {
        const double SA = g_saTot[0], SB = g_saTot[1];
        const double n  = (double)COLS;
        const double ns = (double)NSEG;
        const double m  = ns * (ns - 1.0) * 0.5;
        out[0] = (float)((SA / ns + SB / ns - 2.0 * g_acc[0] / (ns * ns)) / n);
        out[1] = (float)((ns * SA - g_acc[1]) / (n * m));
    }
}

// ---------------------------------------------------------------------------
extern "C" void kernel_launch(void* const* d_in, const int* in_sizes, int n_in,
                              void* d_out, int out_size) {
    const float* fake  = (const float*)d_in[0];
    const float* real_ = (const float*)d_in[1];
    float* out = (float*)d_out;

    zero_kernel<<<(T2 * COLS + 255) / 256, 256>>>();
    psd_kernel<<<PSDBLKS, 256>>>(fake, real_);
    norm_kernel<<<T2 * NORMBLKS, 256>>>();
    dot_kernel<<<COLS / 256, 256>>>();
    final_kernel<<<1, 32>>>(out);
}

// round 6
// speedup vs baseline: 3.6641x; 1.2405x over previous
#include <cuda_runtime.h>
#include <math.h>
#include <float.h>

#define T2       2
#define BATCH    256
#define NSAMP    80000
#define NPERSEG  100
#define NFREQ    51
#define NSEG     800
#define COLS     (BATCH * NFREQ)         // 13056 = 51*256
#define NSPB     2
#define NORMBLKS (NSEG / NSPB)           // 400
#define IPB      24                      // instances per psd block (8 warps x 3)
#define TOT_T    (NSEG * BATCH)          // 204800 per tensor
#define PSDBLKX  ((TOT_T + IPB - 1) / IPB)  // 8534

#define TWO_PI 6.28318530717958647692f

// w10^k = e^{-2*pi*i*k/10} = (C10[k], -S10[k]) — compile-time immediates
__device__ constexpr float C10[10] = {
     1.0f,  0.80901699437494745f,  0.30901699437494745f, -0.30901699437494745f,
    -0.80901699437494745f, -1.0f, -0.80901699437494745f, -0.30901699437494745f,
     0.30901699437494745f,  0.80901699437494745f };
__device__ constexpr float S10[10] = {
     0.0f,  0.58778525229247314f,  0.95105651629515353f,  0.95105651629515353f,
     0.58778525229247314f,  0.0f, -0.58778525229247314f, -0.95105651629515353f,
    -0.95105651629515353f, -0.58778525229247314f };

// Scratch: signed-clamp-log PSD (unnormalized). 83.6 MB.
__device__ float  g_L[T2][NSEG][COLS];
__device__ float  g_colsum[T2][COLS];
__device__ double g_saTot[T2];
__device__ double g_acc[2];   // [0]=sum SF*SR, [1]=sum SF*SF

__device__ __forceinline__ float sclog(float p) {
    float lx = __logf(p);
    float s  = (lx > 0.0f) ? 1.0f : ((lx < 0.0f) ? -1.0f : 0.0f);
    return s * fmaxf(fabsf(lx), 1e-6f);
}

// ---------------------------------------------------------------------------
__global__ __launch_bounds__(256) void zero_kernel() {
    int i = blockIdx.x * 256 + threadIdx.x;
    if (i < T2 * COLS) ((float*)g_colsum)[i] = 0.0f;
    if (i < T2) g_saTot[i] = 0.0;
    if (i < 2)  g_acc[i] = 0.0;
}

// ---------------------------------------------------------------------------
// Kernel A: Welch -> 10x10 CT rDFT(100) with real/conjugate folding.
// Grid: (PSDBLKX, 2); blockIdx.y = tensor. Warp = 3 instances x 10 lanes.
__global__ __launch_bounds__(256) void psd_kernel(const float* __restrict__ fake,
                                                  const float* __restrict__ real_) {
    __shared__ float  wnd[NPERSEG];
    __shared__ float2 tws[NPERSEG];          // e^{-2 pi i k/100}
    __shared__ float  xs[IPB][NPERSEG];
    __shared__ float2 Ysh[IPB][10][6];
    __shared__ float  psd_s[IPB][NFREQ];

    const int tid = threadIdx.x;
    if (tid < NPERSEG) {
        float s, c;
        sincosf(TWO_PI * 0.01f * (float)tid, &s, &c);
        tws[tid] = make_float2(c, -s);
        wnd[tid] = 1.0f - c;                 // hann(periodic)*2
    }
    __syncthreads();

    const int t = blockIdx.y;
    const float* __restrict__ base = (t == 0) ? fake : real_;

    const int warp = tid >> 5, lane = tid & 31;
    const int base_inst = warp * 3;
    const int gbase = blockIdx.x * IPB + base_inst;   // per-tensor instance id

    // ---- stage 0: coalesced load + clamp + window into smem ----
    #pragma unroll
    for (int k = 0; k < 3; ++k) {
        int g = gbase + k;
        if (g >= TOT_T) break;
        int seg = g >> 8, b = g & 255;
        const float* __restrict__ src = base + (size_t)b * NSAMP + seg * NPERSEG;
        for (int i = lane; i < NPERSEG; i += 32)
            xs[base_inst + k][i] = fmaxf(src[i], 1e-6f) * wnd[i];
    }
    __syncwarp();

    const int  ik   = lane / 10;             // 0..2
    const int  role = lane - ik * 10;        // 0..9 (q in stage1, m in stage2)
    const int  inst = base_inst + ik;
    const bool act  = (lane < 30) && (gbase + ik < TOT_T);

    // ---- stage 1: Y[q][r] = sum_a x[10a+q] w10^{ra}, r=0..5, real-folded ----
    if (act) {
        float x[10];
        #pragma unroll
        for (int a = 0; a < 10; ++a) x[a] = xs[inst][a * 10 + role];
        float s1 = x[1] + x[9], d1 = x[1] - x[9];
        float s2 = x[2] + x[8], d2 = x[2] - x[8];
        float s3 = x[3] + x[7], d3 = x[3] - x[7];
        float s4 = x[4] + x[6], d4 = x[4] - x[6];
        float ex = x[0] + x[5], ox = x[0] - x[5];
        float sv[5] = {0.0f, s1, s2, s3, s4};
        float dv[5] = {0.0f, d1, d2, d3, d4};

        // r = 0 and r = 5: pure adds, imag exactly 0
        Ysh[inst][role][0] = make_float2(ex + s1 + s2 + s3 + s4, 0.0f);
        Ysh[inst][role][5] = make_float2(ox - s1 + s2 - s3 + s4, 0.0f);
        #pragma unroll
        for (int r = 1; r < 5; ++r) {
            float re = (r & 1) ? ox : ex;
            float im = 0.0f;
            #pragma unroll
            for (int a = 1; a < 5; ++a) {
                const int k = (r * a) % 10;
                re = fmaf(sv[a],  C10[k], re);
                im = fmaf(dv[a], -S10[k], im);
            }
            Ysh[inst][role][r] = make_float2(re, im);
        }
    }
    __syncwarp();

    // ---- stage 2: Z[q] = tw100[m q] * Y~[q]; DFT-10 over j with q-folding --
    if (act) {
        const int   m  = role;
        const int   c  = (m <= 5) ? m : 10 - m;
        const float cj = (m <= 5) ? 1.0f : -1.0f;
        float Zr[10], Zi[10];
        #pragma unroll
        for (int q = 0; q < 10; ++q) {
            float2 y = Ysh[inst][q][c];
            float  yi = y.y * cj;
            float2 e = tws[m * q];
            Zr[q] = fmaf(e.x, y.x, -e.y * yi);
            Zi[q] = fmaf(e.x, yi,   e.y * y.x);
        }
        // q-folding precompute
        float P[5], Mr[5], Pi[5], Mi[5];
        #pragma unroll
        for (int q = 1; q < 5; ++q) {
            P [q] = Zr[q] + Zr[10 - q];
            Mr[q] = Zr[q] - Zr[10 - q];
            Pi[q] = Zi[q] + Zi[10 - q];
            Mi[q] = Zi[q] - Zi[10 - q];
        }
        const float er = Zr[0] + Zr[5], orr = Zr[0] - Zr[5];
        const float ei = Zi[0] + Zi[5], oi  = Zi[0] - Zi[5];

        float* outp = psd_s[inst];
        // j = 0: all twiddles 1
        {
            float Xr = er + P[1] + P[2] + P[3] + P[4];
            float Xi = ei + Pi[1] + Pi[2] + Pi[3] + Pi[4];
            outp[m] = sclog(fmaf(Xr, Xr, Xi * Xi));
        }
        #pragma unroll
        for (int j = 1; j < 5; ++j) {
            float Xr = (j & 1) ? orr : er;
            float Xi = (j & 1) ? oi  : ei;
            #pragma unroll
            for (int q = 1; q < 5; ++q) {
                const int k = (j * q) % 10;
                Xr = fmaf(P [q],  C10[k], Xr);
                Xr = fmaf(Mi[q],  S10[k], Xr);
                Xi = fmaf(Pi[q],  C10[k], Xi);
                Xi = fmaf(Mr[q], -S10[k], Xi);
            }
            outp[m + 10 * j] = sclog(fmaf(Xr, Xr, Xi * Xi));
        }
        if (m == 0) {   // f = 50: Z real (Zi=0), X[50] = or - P1 + P2 - P3 + P4
            float Xr = orr - P[1] + P[2] - P[3] + P[4];
            outp[50] = sclog(Xr * Xr);
        }
    }
    __syncwarp();

    // ---- stage 3: coalesced write-out ----
    for (int i = lane; i < 3 * NFREQ; i += 32) {
        int k = i / NFREQ, f = i - k * NFREQ;
        int g = gbase + k;
        if (g >= TOT_T) break;
        int seg = g >> 8, b = g & 255;
        g_L[t][seg][b * NFREQ + f] = psd_s[base_inst + k][f];
    }
}

// ---------------------------------------------------------------------------
// Kernel B: fused per-segment normalize + column sums + sum of squares.
__global__ __launch_bounds__(256) void norm_kernel() {
    const int blk = blockIdx.x;
    const int t   = blk / NORMBLKS;
    const int c   = blk % NORMBLKS;
    const int r   = threadIdx.x;

    float csum[NFREQ];
    #pragma unroll
    for (int j = 0; j < NFREQ; ++j) csum[j] = 0.0f;
    float ssq = 0.0f;

    #pragma unroll
    for (int k = 0; k < NSPB; ++k) {
        const int s = c * NSPB + k;
        const float* __restrict__ L = g_L[t][s];
        float v[NFREQ];
        float mn = FLT_MAX, mx = -FLT_MAX;
        #pragma unroll
        for (int j = 0; j < NFREQ; ++j) {
            float x = L[j * 256 + r];
            v[j] = x;
            mn = fminf(mn, x);
            mx = fmaxf(mx, x);
        }
        const float inv = 1.0f / (mx - mn);
        #pragma unroll
        for (int j = 0; j < NFREQ; ++j) {
            float x = (v[j] - mn) * inv;
            csum[j] += x;
            ssq = fmaf(x, x, ssq);
        }
    }

    #pragma unroll
    for (int j = 0; j < NFREQ; ++j)
        atomicAdd(&g_colsum[t][j * 256 + r], csum[j]);

    __shared__ float red[256];
    red[r] = ssq;
    __syncthreads();
    for (int off = 128; off > 0; off >>= 1) {
        if (r < off) red[r] += red[r + off];
        __syncthreads();
    }
    if (r == 0) atomicAdd(&g_saTot[t], (double)red[0]);
}

// ---------------------------------------------------------------------------
__global__ __launch_bounds__(256) void dot_kernel() {
    const int i = blockIdx.x * 256 + threadIdx.x;
    double SF = (double)g_colsum[0][i];
    double SR = (double)g_colsum[1][i];
    double d = SF * SR, q = SF * SF;

    __shared__ double rd[256], rq[256];
    rd[threadIdx.x] = d; rq[threadIdx.x] = q;
    __syncthreads();
    for (int off = 128; off > 0; off >>= 1) {
        if (threadIdx.x < off) {
            rd[threadIdx.x] += rd[threadIdx.x + off];
            rq[threadIdx.x] += rq[threadIdx.x + off];
        }
        __syncthreads();
    }
    if (threadIdx.x == 0) {
        atomicAdd(&g_acc[0], rd[0]);
        atomicAdd(&g_acc[1], rq[0]);
    }
}

// ---------------------------------------------------------------------------
__global__ void final_kernel(float* __restrict__ out) {
    if (threadIdx.x == 0) {
        const double SA = g_saTot[0], SB = g_saTot[1];
        const double n  = (double)COLS;
        const double ns = (double)NSEG;
        const double m  = ns * (ns - 1.0) * 0.5;
        out[0] = (float)((SA / ns + SB / ns - 2.0 * g_acc[0] / (ns * ns)) / n);
        out[1] = (float)((ns * SA - g_acc[1]) / (n * m));
    }
}

// ---------------------------------------------------------------------------
extern "C" void kernel_launch(void* const* d_in, const int* in_sizes, int n_in,
                              void* d_out, int out_size) {
    const float* fake  = (const float*)d_in[0];
    const float* real_ = (const float*)d_in[1];
    float* out = (float*)d_out;

    zero_kernel<<<(T2 * COLS + 255) / 256, 256>>>();
    dim3 pg(PSDBLKX, T2);
    psd_kernel<<<pg, 256>>>(fake, real_);
    norm_kernel<<<T2 * NORMBLKS, 256>>>();
    dot_kernel<<<COLS / 256, 256>>>();
    final_kernel<<<1, 32>>>(out);
}